// round 6
// baseline (speedup 1.0000x reference)
#include <cuda_runtime.h>
#include <cuda_fp16.h>
#include <cstdint>

#define B 32
#define K 1024
#define F 128
#define E 128
#define OUT2 125
#define ALPHA 0.2f

#define CH 64                 // j/k chunk width
#define NCH3 (K / CH)         // 16
#define PPH 72                // A-tile pitch in halves (144 B)
#define XPH 136               // B-tile pitch in halves (272 B)
#define PBUF (128 * PPH * 2)  // 18432 B
#define XBUF (CH * XPH * 2)   // 17408 B
#define NSPLIT 4

// k3f dynamic smem offsets (bytes)
#define OFF_S2 0
#define OFF_S1 4096
#define OFF_INV 4608
#define OFF_P 5120
#define OFF_X (OFF_P + 2 * PBUF)
#define SMEM_K3F (OFF_X + 2 * XBUF)  // 76800
#define SMEM_K4 (2 * (PBUF + XBUF))  // 71680

// -------------------- scratch (device globals, allocation-free) ------------
__device__ float g_w1[F];
__device__ float g_w2[F];
__device__ float g_c[2];
__device__ float g_s1[B * K];
__device__ float g_s2[B * K];
__device__ __half g_xh[(size_t)B * K * F];             // fp16 x  (8 MB)
__device__ __half g_wh[128 * K];                       // fp16 lin2_w (o padded)
__device__ __half g_hh[(size_t)B * K * F];             // fp16 h  (8 MB)
__device__ float g_h2p[NSPLIT][(size_t)B * F * OUT2];  // partials

__device__ __forceinline__ uint32_t smem_u32(const void* p) {
    uint32_t a;
    asm("{ .reg .u64 t; cvta.to.shared.u64 t, %1; cvt.u32.u64 %0, t; }" : "=r"(a) : "l"(p));
    return a;
}
__device__ __forceinline__ void cp16(uint32_t dst, const void* src) {
    asm volatile("cp.async.cg.shared.global [%0], [%1], 16;" :: "r"(dst), "l"(src) : "memory");
}
__device__ __forceinline__ void cp16z(uint32_t dst, const void* src, int bytes) {
    asm volatile("cp.async.cg.shared.global [%0], [%1], 16, %2;"
                 :: "r"(dst), "l"(src), "r"(bytes) : "memory");
}
__device__ __forceinline__ void cp_commit() {
    asm volatile("cp.async.commit_group;" ::: "memory");
}
#define CP_WAIT(n) asm volatile("cp.async.wait_group %0;" :: "n"(n) : "memory")

__device__ __forceinline__ void ldsm4(uint32_t* r, uint32_t addr) {
    asm volatile("ldmatrix.sync.aligned.m8n8.x4.shared.b16 {%0,%1,%2,%3}, [%4];"
                 : "=r"(r[0]), "=r"(r[1]), "=r"(r[2]), "=r"(r[3]) : "r"(addr));
}
__device__ __forceinline__ void ldsm4t(uint32_t* r, uint32_t addr) {
    asm volatile("ldmatrix.sync.aligned.m8n8.x4.trans.shared.b16 {%0,%1,%2,%3}, [%4];"
                 : "=r"(r[0]), "=r"(r[1]), "=r"(r[2]), "=r"(r[3]) : "r"(addr));
}
#define MMA_F16(acc, a, b0, b1)                                            \
    asm volatile(                                                          \
        "mma.sync.aligned.m16n8k16.row.col.f32.f16.f16.f32 "               \
        "{%0,%1,%2,%3}, {%4,%5,%6,%7}, {%8,%9}, {%0,%1,%2,%3};"            \
        : "+f"((acc)[0]), "+f"((acc)[1]), "+f"((acc)[2]), "+f"((acc)[3])   \
        : "r"((a)[0]), "r"((a)[1]), "r"((a)[2]), "r"((a)[3]),              \
          "r"(b0), "r"(b1))

// ---------------------------------------------------------------------------
// k1: fold a: w1 = lin_w^T a1, c1 = lin_b.a1 (and 2)
// ---------------------------------------------------------------------------
__global__ void k1_prep(const float* __restrict__ lin_w,
                        const float* __restrict__ lin_b,
                        const float* __restrict__ a) {
    int f = threadIdx.x;
    __shared__ float sa1[E], sa2[E], red1[E], red2[E];
    float a1v = a[f], a2v = a[E + f];
    sa1[f] = a1v;
    sa2[f] = a2v;
    __syncthreads();
    float acc1 = 0.f, acc2 = 0.f;
#pragma unroll 8
    for (int e = 0; e < E; e++) {
        float lw = lin_w[e * F + f];
        acc1 += lw * sa1[e];
        acc2 += lw * sa2[e];
    }
    g_w1[f] = acc1;
    g_w2[f] = acc2;
    float lb = lin_b[f];
    red1[f] = lb * a1v;
    red2[f] = lb * a2v;
    __syncthreads();
    for (int s = 64; s > 0; s >>= 1) {
        if (f < s) {
            red1[f] += red1[f + s];
            red2[f] += red2[f + s];
        }
        __syncthreads();
    }
    if (f == 0) {
        g_c[0] = red1[0];
        g_c[1] = red2[0];
    }
}

// ---------------------------------------------------------------------------
// k2: s1/s2 row scores (exact fp32). One warp per row.
// ---------------------------------------------------------------------------
__global__ void k2_scores(const float* __restrict__ x) {
    int row = (blockIdx.x * blockDim.x + threadIdx.x) >> 5;
    int lane = threadIdx.x & 31;
    if (row >= B * K) return;
    float4 xv = ((const float4*)(x + (size_t)row * F))[lane];
    float4 w1 = ((const float4*)g_w1)[lane];
    float4 w2 = ((const float4*)g_w2)[lane];
    float d1 = xv.x * w1.x + xv.y * w1.y + xv.z * w1.z + xv.w * w1.w;
    float d2 = xv.x * w2.x + xv.y * w2.y + xv.z * w2.z + xv.w * w2.w;
#pragma unroll
    for (int off = 16; off; off >>= 1) {
        d1 += __shfl_xor_sync(~0u, d1, off);
        d2 += __shfl_xor_sync(~0u, d2, off);
    }
    if (lane == 0) {
        g_s1[row] = d1 + g_c[0];
        g_s2[row] = d2 + g_c[1];
    }
}

// ---------------------------------------------------------------------------
// k2h: fp32 -> fp16 conversion, 8 elems/thread.
// ---------------------------------------------------------------------------
__global__ void k2h_half(const float* __restrict__ src, __half* __restrict__ dst, int n8) {
    int i = blockIdx.x * 256 + threadIdx.x;
    if (i >= n8) return;
    float4 a = ((const float4*)src)[2 * i];
    float4 b = ((const float4*)src)[2 * i + 1];
    __half2 h[4];
    h[0] = __floats2half2_rn(a.x, a.y);
    h[1] = __floats2half2_rn(a.z, a.w);
    h[2] = __floats2half2_rn(b.x, b.y);
    h[3] = __floats2half2_rn(b.z, b.w);
    ((uint4*)dst)[i] = *(uint4*)h;
}

// ---------------------------------------------------------------------------
// k3f: fused softmax + (h = P @ x + x), fp16 MMA.
// Pass 1: row exp-sums. Pass 2: per 64-j chunk compute P (exact fp32 attn out,
// fp16 into smem A-tile), cp.async-stage fp16 x tile, mma.m16n8k16.
// ---------------------------------------------------------------------------
__global__ void __launch_bounds__(256, 2) k3f(const float* __restrict__ x,
                                              const float* __restrict__ bias,
                                              float* __restrict__ attn) {
    extern __shared__ char sm[];
    const uint32_t sbase = smem_u32(sm);
    float* s2s = (float*)(sm + OFF_S2);
    float* s1s = (float*)(sm + OFF_S1);
    float* invs = (float*)(sm + OFF_INV);

    const int tid = threadIdx.x;
    const int wid = tid >> 5, lane = tid & 31;
    const int b = blockIdx.y;
    const int i0 = blockIdx.x * 128;
    const int warp_m = (wid >> 2) * 64;
    const int warp_n = (wid & 3) * 32;
    const int qr = lane >> 2, qc = lane & 3;

    const float* Xb = x + (size_t)b * K * F;
    const __half* Xh = g_xh + (size_t)b * K * F;

    for (int j = tid; j < K; j += 256) s2s[j] = g_s2[b * K + j];
    if (tid < 128) s1s[tid] = g_s1[b * K + i0 + tid];
    __syncthreads();

    // ---- Pass 1: row sums of exp ----
    {
        const float4* s2s4 = (const float4*)s2s;
#pragma unroll 1
        for (int r = 0; r < 16; r++) {
            int row = wid * 16 + r;
            float s1 = s1s[row];
            const float4* brow = (const float4*)(bias + (size_t)(i0 + row) * K);
            float sum = 0.f;
#pragma unroll
            for (int t = 0; t < 8; t++) {
                int j4 = lane + t * 32;
                float4 bv = brow[j4];
                float4 s2v = s2s4[j4];
                float v0 = s1 + s2v.x; v0 = (v0 > 0.f ? v0 : ALPHA * v0) + bv.x;
                float v1 = s1 + s2v.y; v1 = (v1 > 0.f ? v1 : ALPHA * v1) + bv.y;
                float v2 = s1 + s2v.z; v2 = (v2 > 0.f ? v2 : ALPHA * v2) + bv.z;
                float v3 = s1 + s2v.w; v3 = (v3 > 0.f ? v3 : ALPHA * v3) + bv.w;
                sum += __expf(v0) + __expf(v1) + __expf(v2) + __expf(v3);
            }
#pragma unroll
            for (int off = 16; off; off >>= 1) sum += __shfl_xor_sync(~0u, sum, off);
            if (lane == 0) invs[row] = 1.0f / sum;
        }
    }
    __syncthreads();

    // ---- Pass 2 ----
    const int prow = tid >> 1;           // 0..127
    const int pj0 = (tid & 1) * 32;      // 0 or 32 within 64-chunk
    const int jx = tid >> 2, cx = tid & 3;  // X staging: row, col16 base

    // ldmatrix per-lane bases
    const int lrow = (lane & 7) | (((lane >> 3) & 1) << 3);  // 0..15
    const int lhi = (lane >> 4) * 8;                          // 0 or 8

    float acc[4][4][4];
#pragma unroll
    for (int mt = 0; mt < 4; mt++)
#pragma unroll
        for (int nt = 0; nt < 4; nt++)
#pragma unroll
            for (int q = 0; q < 4; q++) acc[mt][nt][q] = 0.f;

#define COMPUTE_P(c, bi)                                                              \
    do {                                                                              \
        float s1 = s1s[prow];                                                         \
        float iv = invs[prow];                                                        \
        const float* brow = bias + (size_t)(i0 + prow) * K + (c) * CH + pj0;          \
        float* arow = attn + ((size_t)(b * K + i0 + prow)) * K + (c) * CH + pj0;      \
        __half2* pd = (__half2*)(sm + OFF_P + (bi) * PBUF + prow * (PPH * 2) + pj0 * 2); \
        const float* s2p = s2s + (c) * CH + pj0;                                      \
        _Pragma("unroll") for (int q = 0; q < 8; q++) {                               \
            float4 bv = *(const float4*)(brow + q * 4);                               \
            float4 s2v = *(const float4*)(s2p + q * 4);                               \
            float4 p;                                                                 \
            float v;                                                                  \
            v = s1 + s2v.x; v = (v > 0.f ? v : ALPHA * v) + bv.x; p.x = __expf(v) * iv; \
            v = s1 + s2v.y; v = (v > 0.f ? v : ALPHA * v) + bv.y; p.y = __expf(v) * iv; \
            v = s1 + s2v.z; v = (v > 0.f ? v : ALPHA * v) + bv.z; p.z = __expf(v) * iv; \
            v = s1 + s2v.w; v = (v > 0.f ? v : ALPHA * v) + bv.w; p.w = __expf(v) * iv; \
            *(float4*)(arow + q * 4) = p;                                             \
            pd[q * 2] = __floats2half2_rn(p.x, p.y);                                  \
            pd[q * 2 + 1] = __floats2half2_rn(p.z, p.w);                              \
        }                                                                             \
    } while (0)

#define STAGE_X(c, bi)                                                                \
    do {                                                                              \
        uint32_t xd = sbase + OFF_X + (bi) * XBUF;                                    \
        _Pragma("unroll") for (int t = 0; t < 4; t++) {                               \
            int col = cx + t * 4;                                                     \
            cp16(xd + jx * (XPH * 2) + col * 16,                                      \
                 Xh + (size_t)((c) * CH + jx) * F + col * 8);                         \
        }                                                                             \
        cp_commit();                                                                  \
    } while (0)

    STAGE_X(0, 0);
    COMPUTE_P(0, 0);
    for (int c = 0; c < NCH3; c++) {
        int bi = c & 1;
        if (c + 1 < NCH3) {
            STAGE_X(c + 1, bi ^ 1);
            COMPUTE_P(c + 1, bi ^ 1);
            CP_WAIT(1);
        } else {
            CP_WAIT(0);
        }
        __syncthreads();
        uint32_t pA = sbase + OFF_P + bi * PBUF + (warp_m + lrow) * (PPH * 2) + lhi * 2;
        uint32_t pB = sbase + OFF_X + bi * XBUF + lrow * (XPH * 2) + (warp_n + lhi) * 2;
#pragma unroll
        for (int kk = 0; kk < 4; kk++) {
            uint32_t af[4][4];
#pragma unroll
            for (int mt = 0; mt < 4; mt++)
                ldsm4(af[mt], pA + mt * 16 * (PPH * 2) + kk * 32);
            uint32_t bf[2][4];
#pragma unroll
            for (int ntp = 0; ntp < 2; ntp++)
                ldsm4t(bf[ntp], pB + kk * 16 * (XPH * 2) + ntp * 32);
#pragma unroll
            for (int mt = 0; mt < 4; mt++)
#pragma unroll
                for (int ntp = 0; ntp < 2; ntp++) {
                    MMA_F16(acc[mt][2 * ntp], af[mt], bf[ntp][0], bf[ntp][1]);
                    MMA_F16(acc[mt][2 * ntp + 1], af[mt], bf[ntp][2], bf[ntp][3]);
                }
        }
        __syncthreads();
    }

    // epilogue: h = acc + x (exact x), store fp16 h for k4
#pragma unroll
    for (int mt = 0; mt < 4; mt++) {
        int r0 = i0 + warp_m + mt * 16 + qr;
#pragma unroll
        for (int nt = 0; nt < 4; nt++) {
            int fc = warp_n + nt * 8 + qc * 2;
            float2 xv0 = *(const float2*)(Xb + (size_t)r0 * F + fc);
            float2 xv1 = *(const float2*)(Xb + (size_t)(r0 + 8) * F + fc);
            *(__half2*)(g_hh + ((size_t)b * K + r0) * F + fc) =
                __floats2half2_rn(acc[mt][nt][0] + xv0.x, acc[mt][nt][1] + xv0.y);
            *(__half2*)(g_hh + ((size_t)b * K + r0 + 8) * F + fc) =
                __floats2half2_rn(acc[mt][nt][2] + xv1.x, acc[mt][nt][3] + xv1.y);
        }
    }
}

// ---------------------------------------------------------------------------
// k4: h2 partial via fp16 mma. A = g_wh [o x k], B = g_hh [k x f].
// ---------------------------------------------------------------------------
__global__ void __launch_bounds__(256, 2) k4_lin2() {
    extern __shared__ char sm[];
    const uint32_t sbase = smem_u32(sm);
    const int tid = threadIdx.x;
    const int wid = tid >> 5, lane = tid & 31;
    const int b = blockIdx.x;
    const int ks = blockIdx.y;
    const int k0 = ks * (K / NSPLIT);
    const int warp_m = (wid >> 2) * 64;
    const int warp_n = (wid & 3) * 32;
    const int qr = lane >> 2, qc = lane & 3;

    const __half* Hb = g_hh + (size_t)b * K * F;
    const int rw = tid >> 1, cw = tid & 1;     // W staging
    const int jx = tid >> 2, cx = tid & 3;     // H staging
    const int lrow = (lane & 7) | (((lane >> 3) & 1) << 3);
    const int lhi = (lane >> 4) * 8;

    float acc[4][4][4];
#pragma unroll
    for (int mt = 0; mt < 4; mt++)
#pragma unroll
        for (int nt = 0; nt < 4; nt++)
#pragma unroll
            for (int q = 0; q < 4; q++) acc[mt][nt][q] = 0.f;

#define STAGE4(c, bi)                                                                 \
    do {                                                                              \
        uint32_t ad = sbase + (bi) * PBUF;                                            \
        uint32_t bd = sbase + 2 * PBUF + (bi) * XBUF;                                 \
        int vb = rw < OUT2 ? 16 : 0;                                                  \
        const __half* wsrc = g_wh + (size_t)(rw < OUT2 ? rw : 0) * K + k0 + (c) * CH; \
        _Pragma("unroll") for (int t = 0; t < 4; t++) {                               \
            int col = cw * 4 + t;                                                     \
            cp16z(ad + rw * (PPH * 2) + col * 16, wsrc + col * 8, vb);                \
        }                                                                             \
        _Pragma("unroll") for (int t = 0; t < 4; t++) {                               \
            int col = cx + t * 4;                                                     \
            cp16(bd + jx * (XPH * 2) + col * 16,                                      \
                 Hb + (size_t)(k0 + (c) * CH + jx) * F + col * 8);                    \
        }                                                                             \
        cp_commit();                                                                  \
    } while (0)

    const int NCH4 = (K / NSPLIT) / CH;  // 4
    STAGE4(0, 0);
    for (int c = 0; c < NCH4; c++) {
        int bi = c & 1;
        if (c + 1 < NCH4) {
            STAGE4(c + 1, bi ^ 1);
            CP_WAIT(1);
        } else {
            CP_WAIT(0);
        }
        __syncthreads();
        uint32_t pA = sbase + bi * PBUF + (warp_m + lrow) * (PPH * 2) + lhi * 2;
        uint32_t pB = sbase + 2 * PBUF + bi * XBUF + lrow * (XPH * 2) + (warp_n + lhi) * 2;
#pragma unroll
        for (int kk = 0; kk < 4; kk++) {
            uint32_t af[4][4];
#pragma unroll
            for (int mt = 0; mt < 4; mt++)
                ldsm4(af[mt], pA + mt * 16 * (PPH * 2) + kk * 32);
            uint32_t bf[2][4];
#pragma unroll
            for (int ntp = 0; ntp < 2; ntp++)
                ldsm4t(bf[ntp], pB + kk * 16 * (XPH * 2) + ntp * 32);
#pragma unroll
            for (int mt = 0; mt < 4; mt++)
#pragma unroll
                for (int ntp = 0; ntp < 2; ntp++) {
                    MMA_F16(acc[mt][2 * ntp], af[mt], bf[ntp][0], bf[ntp][1]);
                    MMA_F16(acc[mt][2 * ntp + 1], af[mt], bf[ntp][2], bf[ntp][3]);
                }
        }
        __syncthreads();
    }

    float* out = g_h2p[ks] + (size_t)b * F * OUT2;
#pragma unroll
    for (int mt = 0; mt < 4; mt++) {
        int o0 = warp_m + mt * 16 + qr;
#pragma unroll
        for (int nt = 0; nt < 4; nt++) {
            int fc = warp_n + nt * 8 + qc * 2;
            if (o0 < OUT2) {
                out[(size_t)fc * OUT2 + o0] = acc[mt][nt][0];
                out[(size_t)(fc + 1) * OUT2 + o0] = acc[mt][nt][1];
            }
            if (o0 + 8 < OUT2) {
                out[(size_t)fc * OUT2 + o0 + 8] = acc[mt][nt][2];
                out[(size_t)(fc + 1) * OUT2 + o0 + 8] = acc[mt][nt][3];
            }
        }
    }
}

// ---------------------------------------------------------------------------
// k5: out = relu(sum partials + lin2_b)
// ---------------------------------------------------------------------------
__global__ void k5_out(const float* __restrict__ lin2_b, float* __restrict__ out) {
    int i = blockIdx.x * 256 + threadIdx.x;
    if (i >= B * F * OUT2) return;
    float v = lin2_b[i % OUT2];
#pragma unroll
    for (int p = 0; p < NSPLIT; p++) v += g_h2p[p][i];
    out[i] = v > 0.f ? v : 0.f;
}

// ---------------------------------------------------------------------------
extern "C" void kernel_launch(void* const* d_in, const int* in_sizes, int n_in,
                              void* d_out, int out_size) {
    const float* x      = (const float*)d_in[0];
    const float* lin_w  = (const float*)d_in[1];
    const float* lin_b  = (const float*)d_in[2];
    const float* a      = (const float*)d_in[3];
    const float* bias   = (const float*)d_in[4];
    const float* lin2_w = (const float*)d_in[5];
    const float* lin2_b = (const float*)d_in[6];
    float* out = (float*)d_out;
    float* out_h2 = out;                           // (B,F,OUT2)
    float* out_attn = out + (size_t)B * F * OUT2;  // (B,K,K)

    cudaFuncSetAttribute(k3f, cudaFuncAttributeMaxDynamicSharedMemorySize, SMEM_K3F);
    cudaFuncSetAttribute(k4_lin2, cudaFuncAttributeMaxDynamicSharedMemorySize, SMEM_K4);

    void* xh = nullptr;
    void* wh = nullptr;
    cudaGetSymbolAddress(&xh, g_xh);
    cudaGetSymbolAddress(&wh, g_wh);

    k1_prep<<<1, 128>>>(lin_w, lin_b, a);
    k2_scores<<<(B * K) / 8, 256>>>(x);
    k2h_half<<<(B * K * F / 8 + 255) / 256, 256>>>(x, (__half*)xh, B * K * F / 8);
    k2h_half<<<(OUT2 * K / 8 + 255) / 256, 256>>>(lin2_w, (__half*)wh, OUT2 * K / 8);
    k3f<<<dim3(K / 128, B), 256, SMEM_K3F>>>(x, bias, out_attn);
    k4_lin2<<<dim3(B, NSPLIT), 256, SMEM_K4>>>();
    k5_out<<<(B * F * OUT2 + 255) / 256, 256>>>(lin2_b, out_h2);
}